// round 6
// baseline (speedup 1.0000x reference)
#include <cuda_runtime.h>
#include <cstdint>

// DynamicRoIAlign: feat (8,256,160,160) f32 NCHW, rois (1024,5) f32,
// SCALE = 160, ALIGNED = False -> ix = fx - 0.5 (exact collapse).
// Output (K, 256, 14, 14) f32.
//
// R5: 5-tap vectorized gather. Per output row-pair we load one aligned
// float4 at e = x0c & ~3 per row and dot with a precomputed per-position
// coefficient vector (x-weights scattered onto taps 0..4; tap 4 is a
// predicated scalar load, fires only when x0c % 4 == 3 in the interior).
// Cuts L1TEX wavefronts ~4L -> ~2.5L vs the 4-scalar-LDG version
// (L1 was the measured bottleneck at 78.7%).

#define OH 14
#define OW 14
#define NPOS (OH * OW)        // 196
#define CCH 256
#define FH 160
#define FW 160
#define FHW (FH * FW)         // 25600
#define SCALE 160.0f

__global__ __launch_bounds__(256, 6)
void roi_align_kernel(const float* __restrict__ feat,
                      const float* __restrict__ rois,
                      float* __restrict__ out)
{
    const int k = blockIdx.x;
    const int t = threadIdx.x;

    __shared__ int2   s_eb[NPOS];    // aligned row bases: y0c*W + e, y1c*W + e
    __shared__ float4 s_cw[NPOS];    // x-coefficients for taps 0..3
    __shared__ float4 s_ax[NPOS];    // {c4, ry0, ry1, unused}
    __shared__ float  s_roi[5];
    __shared__ int    s_base;        // b * C * H * W

    if (t < 5) s_roi[t] = rois[k * 5 + t];
    __syncthreads();

    if (t < NPOS) {
        const int oy = t / OW;
        const int ox = t - oy * OW;

        const float x1 = s_roi[1] * SCALE;
        const float y1 = s_roi[2] * SCALE;
        const float x2 = s_roi[3] * SCALE;
        const float y2 = s_roi[4] * SCALE;

        const float gx = (float)ox * (1.0f / (OW - 1));
        const float gy = (float)oy * (1.0f / (OH - 1));

        // ALIGNED=False: ix = fx - 0.5, iy = fy - 0.5
        const float ix = (x1 + gx * (x2 - x1)) - 0.5f;
        const float iy = (y1 + gy * (y2 - y1)) - 0.5f;

        const float fx0 = floorf(ix);
        const float fy0 = floorf(iy);
        const int   x0  = (int)fx0;
        const int   y0  = (int)fy0;
        const int   x1i = x0 + 1;
        const int   y1i = y0 + 1;

        const float wx1 = ix - fx0;
        const float wx0 = 1.0f - wx1;
        const float wy1 = iy - fy0;
        const float wy0 = 1.0f - wy1;

        const float vx0 = (x0  >= 0 && x0  < FW) ? 1.0f : 0.0f;
        const float vx1 = (x1i >= 0 && x1i < FW) ? 1.0f : 0.0f;
        const float vy0 = (y0  >= 0 && y0  < FH) ? 1.0f : 0.0f;
        const float vy1 = (y1i >= 0 && y1i < FH) ? 1.0f : 0.0f;

        const int x0c = min(max(x0,  0), FW - 1);
        const int x1c = min(max(x1i, 0), FW - 1);
        const int y0c = min(max(y0,  0), FH - 1);
        const int y1c = min(max(y1i, 0), FH - 1);

        // Aligned 4-float window containing x0c; x1c is at tap j0..j0+1 (<=4).
        const int e  = x0c & ~3;
        const int j0 = x0c - e;          // 0..3
        const int j1 = x1c - e;          // 0..4

        float c[5] = {0.f, 0.f, 0.f, 0.f, 0.f};
        c[j0] += wx0 * vx0;
        c[j1] += wx1 * vx1;

        s_eb[t] = make_int2(y0c * FW + e, y1c * FW + e);
        s_cw[t] = make_float4(c[0], c[1], c[2], c[3]);
        s_ax[t] = make_float4(c[4], wy0 * vy0, wy1 * vy1, 0.f);
    }
    if (t == 0) s_base = (int)s_roi[0] * (CCH * FHW);
    __syncthreads();

    const float* fb   = feat + s_base;
    float*       outk = out + (size_t)k * (CCH * NPOS);

    // 50176 outputs per roi; out-index-linear -> coalesced STG.32.
    #pragma unroll 2
    for (int idx = t; idx < CCH * NPOS; idx += 256) {
        const int c   = idx / NPOS;
        const int pos = idx - c * NPOS;

        const int2   eb = s_eb[pos];
        const float4 cw = s_cw[pos];
        const float4 ax = s_ax[pos];
        const float* f  = fb + c * FHW;

        const float4 V0 = __ldg((const float4*)(f + eb.x));
        const float4 V1 = __ldg((const float4*)(f + eb.y));

        float d0 = V0.x * cw.x + V0.y * cw.y + V0.z * cw.z + V0.w * cw.w;
        float d1 = V1.x * cw.x + V1.y * cw.y + V1.z * cw.z + V1.w * cw.w;

        if (ax.x != 0.0f) {           // tap 4: x0c%4==3 interior case (~25%)
            d0 += __ldg(f + eb.x + 4) * ax.x;
            d1 += __ldg(f + eb.y + 4) * ax.x;
        }

        outk[idx] = d0 * ax.y + d1 * ax.z;
    }
}

extern "C" void kernel_launch(void* const* d_in, const int* in_sizes, int n_in,
                              void* d_out, int out_size)
{
    const float* feat = (const float*)d_in[0];
    const float* rois = (const float*)d_in[1];
    float*       out  = (float*)d_out;

    const int K = in_sizes[1] / 5;   // 1024

    roi_align_kernel<<<K, 256>>>(feat, rois, out);
}

// round 16
// speedup vs baseline: 1.3000x; 1.3000x over previous
#include <cuda_runtime.h>
#include <cstdint>

// DynamicRoIAlign: feat (8,256,160,160) f32 NCHW, rois (1024,5) f32,
// SCALE = 160, ALIGNED = False -> ix = fx - 0.5 (exact collapse).
// Output (K, 256, 14, 14) f32.
//
// R7: 5-tap vectorized gather, BRANCHLESS. Two aligned LDG.128 (one per
// y-row) cover both x-taps for lanes with x0c%4 != 3; the spill tap-4 is a
// per-lane PREDICATED scalar load (ternary -> @P LDG, predicated-off lanes
// issue no requests -> fix-up instruction touches only ~25% of lanes'
// lines). vs R4's 4 scalar LDGs: ~19 -> ~14 L1 wavefronts per warp-iter.
// R5's failure (319us) was a warp-level branch + occ-6 + no load batching.

#define OH 14
#define OW 14
#define NPOS (OH * OW)        // 196
#define CCH 256
#define FH 160
#define FW 160
#define FHW (FH * FW)         // 25600
#define SCALE 160.0f

__global__ __launch_bounds__(256, 8)
void roi_align_kernel(const float* __restrict__ feat,
                      const float* __restrict__ rois,
                      float* __restrict__ out)
{
    const int k = blockIdx.x;
    const int t = threadIdx.x;

    __shared__ int2   s_eb[NPOS];    // aligned row bases: y0c*W + e, y1c*W + e
    __shared__ float4 s_cw[NPOS];    // x-coefficients for taps 0..3
    __shared__ float4 s_ax[NPOS];    // {c4, ry0, ry1, 0}
    __shared__ float  s_roi[5];
    __shared__ int    s_base;        // b * C * H * W

    if (t < 5) s_roi[t] = rois[k * 5 + t];
    __syncthreads();

    if (t < NPOS) {
        const int oy = t / OW;
        const int ox = t - oy * OW;

        const float x1 = s_roi[1] * SCALE;
        const float y1 = s_roi[2] * SCALE;
        const float x2 = s_roi[3] * SCALE;
        const float y2 = s_roi[4] * SCALE;

        const float gx = (float)ox * (1.0f / (OW - 1));
        const float gy = (float)oy * (1.0f / (OH - 1));

        // ALIGNED=False: ix = fx - 0.5, iy = fy - 0.5
        const float ix = (x1 + gx * (x2 - x1)) - 0.5f;
        const float iy = (y1 + gy * (y2 - y1)) - 0.5f;

        const float fx0 = floorf(ix);
        const float fy0 = floorf(iy);
        const int   x0  = (int)fx0;
        const int   y0  = (int)fy0;
        const int   x1i = x0 + 1;
        const int   y1i = y0 + 1;

        const float wx1 = ix - fx0;
        const float wx0 = 1.0f - wx1;
        const float wy1 = iy - fy0;
        const float wy0 = 1.0f - wy1;

        const float vx0 = (x0  >= 0 && x0  < FW) ? 1.0f : 0.0f;
        const float vx1 = (x1i >= 0 && x1i < FW) ? 1.0f : 0.0f;
        const float vy0 = (y0  >= 0 && y0  < FH) ? 1.0f : 0.0f;
        const float vy1 = (y1i >= 0 && y1i < FH) ? 1.0f : 0.0f;

        const int x0c = min(max(x0,  0), FW - 1);
        const int x1c = min(max(x1i, 0), FW - 1);
        const int y0c = min(max(y0,  0), FH - 1);
        const int y1c = min(max(y1i, 0), FH - 1);

        // Aligned 4-float window containing x0c; x1c lands on tap j1 <= 4.
        const int e  = x0c & ~3;
        const int j0 = x0c - e;          // 0..3
        const int j1 = x1c - e;          // 0..4

        float c[5] = {0.f, 0.f, 0.f, 0.f, 0.f};
        c[j0] += wx0 * vx0;
        c[j1] += wx1 * vx1;
        // When c[4] != 0: x1c = e+4 <= 159, so the e+4 load stays in-row.

        s_eb[t] = make_int2(y0c * FW + e, y1c * FW + e);
        s_cw[t] = make_float4(c[0], c[1], c[2], c[3]);
        s_ax[t] = make_float4(c[4], wy0 * vy0, wy1 * vy1, 0.f);
    }
    if (t == 0) s_base = (int)s_roi[0] * (CCH * FHW);
    __syncthreads();

    const float* fb   = feat + s_base;
    float*       outk = out + (size_t)k * (CCH * NPOS);

    // 50176 outputs per roi; out-index-linear -> coalesced STG.32.
    // Branchless body -> ptxas front-batches loads (8 LDGs in flight / thread
    // at unroll 2).
    #pragma unroll 2
    for (int idx = t; idx < CCH * NPOS; idx += 256) {
        const int c   = idx / NPOS;
        const int pos = idx - c * NPOS;

        const int2   eb = s_eb[pos];
        const float4 cw = s_cw[pos];
        const float4 ax = s_ax[pos];
        const float* f  = fb + c * FHW;

        const bool  p  = (ax.x != 0.0f);
        const float4 V0 = __ldg((const float4*)(f + eb.x));
        const float4 V1 = __ldg((const float4*)(f + eb.y));
        const float  E0 = p ? __ldg(f + eb.x + 4) : 0.0f;   // @P LDG (per-lane)
        const float  E1 = p ? __ldg(f + eb.y + 4) : 0.0f;

        float d0 = V0.x * cw.x + V0.y * cw.y + V0.z * cw.z + V0.w * cw.w
                 + E0 * ax.x;
        float d1 = V1.x * cw.x + V1.y * cw.y + V1.z * cw.z + V1.w * cw.w
                 + E1 * ax.x;

        outk[idx] = d0 * ax.y + d1 * ax.z;
    }
}

extern "C" void kernel_launch(void* const* d_in, const int* in_sizes, int n_in,
                              void* d_out, int out_size)
{
    const float* feat = (const float*)d_in[0];
    const float* rois = (const float*)d_in[1];
    float*       out  = (float*)d_out;

    const int K = in_sizes[1] / 5;   // 1024

    roi_align_kernel<<<K, 256>>>(feat, rois, out);
}